// round 8
// baseline (speedup 1.0000x reference)
#include <cuda_runtime.h>
#include <math.h>

#define NB 2049
#define S_ 2048
#define W_ 64
#define D_ 300
#define M_ 100
#define H_ 8
#define D2_ 200
#define V_ 50000
#define RSQ 0.07071067811865475f   // 1/sqrt(200)

// ----------------------------- device scratch ------------------------------
__device__ float g_EW[V_ * 800];          // emb @ [w_ih_f | w_ih_b]^T
__device__ float g_WhhT[2 * M_ * 400];    // [dir][m][j] = w_hh[dir][j][m]
__device__ float g_bc[800];               // b_ih + b_hh per dir
__device__ float g_hid[NB * D2_];         // [h_f | h_b]
__device__ float g_cst[2 * NB * M_];      // cell states
__device__ float g_hv[D2_];
__device__ float g_logit[S_];
__device__ float g_prob[S_];
__device__ float g_att[S_ * D2_];
__device__ float g_Qa[H_ * S_ * D2_];
__device__ float g_Ka[H_ * S_ * D2_];
__device__ float g_Va[H_ * S_ * D2_];
__device__ float g_Qc[H_ * S_ * D2_];
__device__ float g_Kc[H_ * S_ * D2_];
__device__ float g_Vc[H_ * S_ * D2_];
__device__ float g_SC[33554432];          // 8 * 2048 * 2048 scores -> P in place
__device__ float g_mx[H_ * S_];
__device__ float g_iZ[H_ * S_];
__device__ float g_cat[S_ * H_ * D2_];    // out in cat layout [s][h*200+o]
__device__ float g_mh[S_ * D2_];
__device__ float g_fp[2 * 8 * D2_];
__device__ int   g_idx[2][S_];
__device__ int   g_n[2];

// ------------------------------ generic SGEMM ------------------------------
// C[M,N] = A[M,K] * op(B) (+ bias[bz*sBias + n]); transB: B is (N,K) row-major.
// limBr>=0: lim=g_n[limBr]; limRows/limCols skip tiles past lim; capK caps K
// to align16(lim). epi: 1 -> v*RSQ ; 2 -> (1-v)*RSQ.
#define BM 64
#define BN 64
#define BK 16

__global__ void sgemm(const float* __restrict__ A, int lda, long long sA,
                      const float* __restrict__ B, int ldb, long long sB, int transB,
                      float* __restrict__ C, int ldc, long long sC,
                      int M, int N, int K,
                      const float* __restrict__ bias, int sBias,
                      int limBr, int limRows, int limCols, int capK, int epi)
{
    int bz = blockIdx.z;
    int m0 = blockIdx.y * BM;
    int n0 = blockIdx.x * BN;
    if (limBr >= 0) {
        int lim = g_n[limBr];
        if (limRows && m0 >= lim) return;
        if (limCols && n0 >= lim) return;
        if (capK) { int kc = (lim + 15) & ~15; if (kc < K) K = kc; }
    }
    A += (long long)bz * sA;
    B += (long long)bz * sB;
    C += (long long)bz * sC;

    __shared__ __align__(16) float As[BK][BM + 4];
    __shared__ __align__(16) float Bs[BK][BN + 4];
    int tid = threadIdx.x;            // 256 threads
    int tr = tid >> 4, tc = tid & 15;
    float acc[4][4] = {};

    for (int k0 = 0; k0 < K; k0 += BK) {
#pragma unroll
        for (int i = 0; i < 4; i++) {
            int e = tid + i * 256;
            int m = e >> 4, k = e & 15;
            int gm = m0 + m, gk = k0 + k;
            As[k][m] = (gm < M && gk < K) ? A[(long long)gm * lda + gk] : 0.f;
        }
        if (transB) {
#pragma unroll
            for (int i = 0; i < 4; i++) {
                int e = tid + i * 256;
                int nn = e >> 4, k = e & 15;
                int gn = n0 + nn, gk = k0 + k;
                Bs[k][nn] = (gn < N && gk < K) ? B[(long long)gn * ldb + gk] : 0.f;
            }
        } else {
#pragma unroll
            for (int i = 0; i < 4; i++) {
                int e = tid + i * 256;
                int k = e >> 6, nn = e & 63;
                int gk = k0 + k, gn = n0 + nn;
                Bs[k][nn] = (gk < K && gn < N) ? B[(long long)gk * ldb + gn] : 0.f;
            }
        }
        __syncthreads();
#pragma unroll
        for (int k = 0; k < BK; k++) {
            float4 av = *reinterpret_cast<const float4*>(&As[k][tr * 4]);
            float4 bv = *reinterpret_cast<const float4*>(&Bs[k][tc * 4]);
            float a0 = av.x, a1 = av.y, a2 = av.z, a3 = av.w;
            float b0 = bv.x, b1 = bv.y, b2 = bv.z, b3 = bv.w;
            acc[0][0] += a0 * b0; acc[0][1] += a0 * b1; acc[0][2] += a0 * b2; acc[0][3] += a0 * b3;
            acc[1][0] += a1 * b0; acc[1][1] += a1 * b1; acc[1][2] += a1 * b2; acc[1][3] += a1 * b3;
            acc[2][0] += a2 * b0; acc[2][1] += a2 * b1; acc[2][2] += a2 * b2; acc[2][3] += a2 * b3;
            acc[3][0] += a3 * b0; acc[3][1] += a3 * b1; acc[3][2] += a3 * b2; acc[3][3] += a3 * b3;
        }
        __syncthreads();
    }
#pragma unroll
    for (int i = 0; i < 4; i++) {
        int gm = m0 + tr * 4 + i;
        if (gm >= M) continue;
#pragma unroll
        for (int j = 0; j < 4; j++) {
            int gn = n0 + tc * 4 + j;
            if (gn >= N) continue;
            float v = acc[i][j];
            if (bias) v += bias[bz * sBias + gn];
            if (epi == 1) v *= RSQ;
            else if (epi == 2) v = (1.f - v) * RSQ;
            C[(long long)gm * ldc + gn] = v;
        }
    }
}

// ---------------------------------- prep -----------------------------------
__global__ void prep(const float* __restrict__ whf, const float* __restrict__ whb,
                     const float* __restrict__ bihf, const float* __restrict__ bhhf,
                     const float* __restrict__ bihb, const float* __restrict__ bhhb)
{
    int i = blockIdx.x * 256 + threadIdx.x;
    if (i < 2 * M_ * 400) {
        int dir = i / (M_ * 400);
        int r = i - dir * (M_ * 400);
        int m = r / 400;
        int j = r - m * 400;
        const float* wh = dir ? whb : whf;
        g_WhhT[i] = wh[j * M_ + m];
    }
    if (i < 800) {
        int dir = i / 400, j = i - dir * 400;
        g_bc[i] = dir ? (bihb[j] + bhhb[j]) : (bihf[j] + bhhf[j]);
    }
    if (i < NB * D2_) g_hid[i] = 0.f;
    if (i < 2 * NB * M_) g_cst[i] = 0.f;
}

// -------------------------------- LSTM step --------------------------------
__global__ void lstm_step(const int* __restrict__ rsent, const int* __restrict__ body, int t)
{
    int dir = blockIdx.y;
    int n0 = blockIdx.x * 8;
    int tid = threadIdx.x;          // 128
    __shared__ float hs[8][M_];
    __shared__ float gs[8][400];
    __shared__ int toks[8];
    int w = dir ? (63 - t) : t;
    if (tid < 8) {
        int n = n0 + tid;
        int tk = 0;
        if (n < NB) tk = (n == 0) ? rsent[w] : body[(n - 1) * W_ + w];
        toks[tid] = tk;
    }
    for (int e = tid; e < 8 * M_; e += 128) {
        int r = e / M_, m = e - r * M_;
        int n = n0 + r;
        hs[r][m] = (n < NB) ? g_hid[n * D2_ + dir * M_ + m] : 0.f;
    }
    __syncthreads();

    float acc[4][8];
#pragma unroll
    for (int jo = 0; jo < 4; jo++)
#pragma unroll
        for (int r = 0; r < 8; r++) acc[jo][r] = 0.f;

    const float* Wp = g_WhhT + dir * (M_ * 400);
    for (int m = 0; m < M_; m++) {
        float hh[8];
#pragma unroll
        for (int r = 0; r < 8; r++) hh[r] = hs[r][m];
#pragma unroll
        for (int jo = 0; jo < 4; jo++) {
            int j = tid + jo * 128;
            float wv = (j < 400) ? Wp[m * 400 + j] : 0.f;
#pragma unroll
            for (int r = 0; r < 8; r++) acc[jo][r] += wv * hh[r];
        }
    }
#pragma unroll
    for (int jo = 0; jo < 4; jo++) {
        int j = tid + jo * 128;
        if (j >= 400) continue;
        float bb = g_bc[dir * 400 + j];
#pragma unroll
        for (int r = 0; r < 8; r++) {
            int n = n0 + r;
            if (n >= NB) continue;
            gs[r][j] = acc[jo][r] + bb + g_EW[(long long)toks[r] * 800 + dir * 400 + j];
        }
    }
    __syncthreads();
    for (int e = tid; e < 800; e += 128) {
        int r = e / 100, m2 = e - r * 100;
        int n = n0 + r;
        if (n >= NB) continue;
        float gi = gs[r][m2], gf = gs[r][100 + m2], gg = gs[r][200 + m2], go = gs[r][300 + m2];
        long long ci = (long long)dir * NB * M_ + (long long)n * M_ + m2;
        float c = g_cst[ci];
        float fi = 1.f / (1.f + expf(-gi));
        float ff = 1.f / (1.f + expf(-gf));
        float fo = 1.f / (1.f + expf(-go));
        c = ff * c + fi * tanhf(gg);
        g_cst[ci] = c;
        g_hid[n * D2_ + dir * M_ + m2] = fo * tanhf(c);
    }
}

// ----------------------------- sim / partition -----------------------------
__global__ void hv_k(const float* __restrict__ simw)
{
    int b = threadIdx.x;
    if (b >= D2_) return;
    float a = 0.f;
    for (int i = 0; i < D2_; i++) a += g_hid[i] * simw[i * D2_ + b];
    g_hv[b] = a;
}

__global__ void logits_k(const float* __restrict__ simb)
{
    __shared__ float hv[D2_];
    int tid = threadIdx.x;
    if (tid < D2_) hv[tid] = g_hv[tid];
    __syncthreads();
    int warp = tid >> 5, lane = tid & 31;
    int s = blockIdx.x * 8 + warp;
    const float* row = g_hid + (long long)(s + 1) * D2_;
    float a = 0.f;
    for (int b = lane; b < D2_; b += 32) a += hv[b] * row[b];
#pragma unroll
    for (int o = 16; o; o >>= 1) a += __shfl_down_sync(0xffffffffu, a, o);
    if (lane == 0) g_logit[s] = a + simb[0];
}

__global__ void softpart()
{
    __shared__ float sg[S_];
    __shared__ float redm[32];
    __shared__ float reds[32];
    __shared__ int cnt[1024];
    int tid = threadIdx.x;           // 1024
    for (int s = tid; s < S_; s += 1024) {
        float l = g_logit[s];
        sg[s] = 1.f / (1.f + expf(-l));
    }
    __syncthreads();
    // max
    float m = fmaxf(sg[tid], sg[tid + 1024]);
#pragma unroll
    for (int o = 16; o; o >>= 1) m = fmaxf(m, __shfl_xor_sync(0xffffffffu, m, o));
    if ((tid & 31) == 0) redm[tid >> 5] = m;
    __syncthreads();
    if (tid < 32) {
        float v = redm[tid];
#pragma unroll
        for (int o = 16; o; o >>= 1) v = fmaxf(v, __shfl_xor_sync(0xffffffffu, v, o));
        if (tid == 0) redm[0] = v;
    }
    __syncthreads();
    float mx = redm[0];
    // sum
    float z = expf(sg[tid] - mx) + expf(sg[tid + 1024] - mx);
#pragma unroll
    for (int o = 16; o; o >>= 1) z += __shfl_xor_sync(0xffffffffu, z, o);
    if ((tid & 31) == 0) reds[tid >> 5] = z;
    __syncthreads();
    if (tid < 32) {
        float v = reds[tid];
#pragma unroll
        for (int o = 16; o; o >>= 1) v += __shfl_xor_sync(0xffffffffu, v, o);
        if (tid == 0) reds[0] = v;
    }
    __syncthreads();
    float invZ = 1.f / reds[0];
    for (int s = tid; s < S_; s += 1024) g_prob[s] = expf(sg[s] - mx) * invZ;

    // stable partition by mask = sig >= 0.5
    int a = (sg[2 * tid] >= 0.5f) ? 1 : 0;
    int b = (sg[2 * tid + 1] >= 0.5f) ? 1 : 0;
    cnt[tid] = a + b;
    __syncthreads();
    for (int off = 1; off < 1024; off <<= 1) {
        int v = cnt[tid];
        int u = (tid >= off) ? cnt[tid - off] : 0;
        __syncthreads();
        cnt[tid] = v + u;
        __syncthreads();
    }
    int pre = (tid > 0) ? cnt[tid - 1] : 0;
    int tot = cnt[1023];
    int s0 = 2 * tid, s1 = 2 * tid + 1;
    if (a) g_idx[0][pre] = s0; else g_idx[1][s0 - pre] = s0;
    int pre1 = pre + a;
    if (b) g_idx[0][pre1] = s1; else g_idx[1][s1 - pre1] = s1;
    if (tid == 0) { g_n[0] = tot; g_n[1] = S_ - tot; }
}

__global__ void attend_k()
{
    int s = blockIdx.x;
    float p = g_prob[s];
    for (int o = threadIdx.x; o < D2_; o += 256)
        g_att[s * D2_ + o] = p * g_hid[(s + 1) * D2_ + o];
}

// -------------------------- branch-local kernels ---------------------------
__global__ void compact(int br)
{
    int p = blockIdx.x;
    if (p >= g_n[br]) return;
    int src = g_idx[br][p];
    for (int e = threadIdx.x; e < H_ * D2_; e += 192) {
        int h = e / D2_, o = e - h * D2_;
        long long di = (long long)h * (S_ * D2_) + (long long)p * D2_ + o;
        long long si = (long long)h * (S_ * D2_) + (long long)src * D2_ + o;
        g_Qc[di] = g_Qa[si];
        g_Kc[di] = g_Ka[si];
        g_Vc[di] = g_Va[si];
    }
}

__global__ void colstats(int br)
{
    int n = g_n[br];
    int t = blockIdx.x * 128 + threadIdx.x;
    if (t >= n) return;
    int h = blockIdx.y;
    const float* base = g_SC + (long long)h * S_ * S_ + t;
    float m = -1e30f;
    for (int s = 0; s < n; s++) m = fmaxf(m, base[(long long)s * S_]);
    float z = 0.f;
    for (int s = 0; s < n; s++) z += expf(base[(long long)s * S_] - m);
    g_mx[h * S_ + t] = m;
    g_iZ[h * S_ + t] = 1.f / z;
}

__global__ void pnorm(int br)
{
    int n = g_n[br];
    int s = blockIdx.y;
    if (s >= n) return;
    int capn = (n + 15) & ~15;
    int t = blockIdx.x * 256 + threadIdx.x;
    if (t >= capn) return;
    int h = blockIdx.z;
    long long ix = (long long)h * S_ * S_ + (long long)s * S_ + t;
    float v = 0.f;
    if (t < n) v = expf(g_SC[ix] - g_mx[h * S_ + t]) * g_iZ[h * S_ + t];
    g_SC[ix] = v;
}

__global__ void featpart(const float* __restrict__ fw, int br)
{
    int n = g_n[br];
    int j = blockIdx.x;
    int ch = blockIdx.y;
    int per = (n + 7) / 8;
    int s0 = ch * per;
    int s1 = s0 + per; if (s1 > n) s1 = n;
    if (s0 > n) s0 = n;
    float acc = 0.f;
    const float* base = fw + (long long)j * (S_ * D2_);
    for (long long e = (long long)s0 * D2_ + threadIdx.x; e < (long long)s1 * D2_; e += 256)
        acc += g_mh[e] * base[e];
    __shared__ float red[8];
#pragma unroll
    for (int o = 16; o; o >>= 1) acc += __shfl_xor_sync(0xffffffffu, acc, o);
    if ((threadIdx.x & 31) == 0) red[threadIdx.x >> 5] = acc;
    __syncthreads();
    if (threadIdx.x < 8) {
        float v = red[threadIdx.x];
#pragma unroll
        for (int o = 4; o; o >>= 1) v += __shfl_xor_sync(0x000000ffu, v, o);
        if (threadIdx.x == 0) g_fp[(br * 8 + ch) * D2_ + j] = v;
    }
}

__global__ void finalize(const float* __restrict__ fb, float* __restrict__ out)
{
    int i = blockIdx.x * 256 + threadIdx.x;
    if (i >= 400) return;
    int br = i / 200, j = i - br * 200;
    float a = fb[j];
    for (int c = 0; c < 8; c++) a += g_fp[(br * 8 + c) * D2_ + j];
    out[i] = a;
}

// --------------------------------- launcher --------------------------------
extern "C" void kernel_launch(void* const* d_in, const int* in_sizes, int n_in,
                              void* d_out, int out_size)
{
    const int*   rsent = (const int*)d_in[0];
    const int*   body  = (const int*)d_in[1];
    const float* emb   = (const float*)d_in[2];
    const float* wihf  = (const float*)d_in[3];
    const float* whhf  = (const float*)d_in[4];
    const float* bihf  = (const float*)d_in[5];
    const float* bhhf  = (const float*)d_in[6];
    const float* wihb  = (const float*)d_in[7];
    const float* whhb  = (const float*)d_in[8];
    const float* bihb  = (const float*)d_in[9];
    const float* bhhb  = (const float*)d_in[10];
    const float* simw  = (const float*)d_in[11];
    const float* simb  = (const float*)d_in[12];
    const float* qw    = (const float*)d_in[13];
    const float* qb    = (const float*)d_in[14];
    const float* kw    = (const float*)d_in[15];
    const float* kb    = (const float*)d_in[16];
    const float* vw    = (const float*)d_in[17];
    const float* vb    = (const float*)d_in[18];
    const float* cw    = (const float*)d_in[19];
    const float* cb    = (const float*)d_in[20];
    const float* fw    = (const float*)d_in[21];
    const float* fb    = (const float*)d_in[22];
    float* out = (float*)d_out;

    float *pEW, *pAtt, *pQa, *pKa, *pVa, *pQc, *pKc, *pVc, *pSC, *pCat, *pMh;
    cudaGetSymbolAddress((void**)&pEW, g_EW);
    cudaGetSymbolAddress((void**)&pAtt, g_att);
    cudaGetSymbolAddress((void**)&pQa, g_Qa);
    cudaGetSymbolAddress((void**)&pKa, g_Ka);
    cudaGetSymbolAddress((void**)&pVa, g_Va);
    cudaGetSymbolAddress((void**)&pQc, g_Qc);
    cudaGetSymbolAddress((void**)&pKc, g_Kc);
    cudaGetSymbolAddress((void**)&pVc, g_Vc);
    cudaGetSymbolAddress((void**)&pSC, g_SC);
    cudaGetSymbolAddress((void**)&pCat, g_cat);
    cudaGetSymbolAddress((void**)&pMh, g_mh);

    prep<<<1601, 256>>>(whhf, whhb, bihf, bhhf, bihb, bhhb);

    // EW = emb @ w_ih^T  (per direction)
    dim3 ge(7, 782, 1);
    sgemm<<<ge, 256>>>(emb, 300, 0, wihf, 300, 0, 1, pEW,       800, 0,
                       V_, 400, 300, nullptr, 0, -1, 0, 0, 0, 0);
    sgemm<<<ge, 256>>>(emb, 300, 0, wihb, 300, 0, 1, pEW + 400, 800, 0,
                       V_, 400, 300, nullptr, 0, -1, 0, 0, 0, 0);

    for (int t = 0; t < 64; t++)
        lstm_step<<<dim3(257, 2), 128>>>(rsent, body, t);

    hv_k<<<1, 256>>>(simw);
    logits_k<<<256, 256>>>(simb);
    softpart<<<1, 1024>>>();
    attend_k<<<2048, 256>>>();

    // Q/K/V on full attend, h-batched (z=8)
    dim3 gq(4, 32, 8);
    sgemm<<<gq, 256>>>(pAtt, 200, 0, qw, 200, 40000LL, 1, pQa, 200, 409600LL,
                       S_, 200, 200, qb, 200, -1, 0, 0, 0, 0);
    sgemm<<<gq, 256>>>(pAtt, 200, 0, kw, 200, 40000LL, 1, pKa, 200, 409600LL,
                       S_, 200, 200, kb, 200, -1, 0, 0, 0, 0);
    sgemm<<<gq, 256>>>(pAtt, 200, 0, vw, 200, 40000LL, 1, pVa, 200, 409600LL,
                       S_, 200, 200, vb, 200, -1, 0, 0, 0, 0);

    for (int br = 0; br < 2; br++) {
        compact<<<2048, 192>>>(br);

        // scores[h,s,t] = Qc[h,s] . Kc[h,t], epilogue (indicator + 1/sqrt(D2))
        dim3 gs(32, 32, 8);
        sgemm<<<gs, 256>>>(pQc, 200, 409600LL, pKc, 200, 409600LL, 1,
                           pSC, 2048, 4194304LL, S_, S_, 200,
                           nullptr, 0, br, 1, 1, 0, (br == 0) ? 1 : 2);

        colstats<<<dim3(16, 8), 128>>>(br);
        pnorm<<<dim3(8, 2048, 8), 256>>>(br);

        // out[h,s,o] = P[h,s,:] @ Vc[h,:,o]  -> written directly in cat layout
        dim3 go(4, 32, 8);
        sgemm<<<go, 256>>>(pSC, 2048, 4194304LL, pVc, 200, 409600LL, 0,
                           pCat, 1600, 200LL, S_, 200, S_,
                           nullptr, 0, br, 1, 0, 1, 0);

        // mh = cat @ concat_w^T + concat_b
        dim3 gm(4, 32, 1);
        sgemm<<<gm, 256>>>(pCat, 1600, 0, cw, 1600, 0, 1, pMh, 200, 0,
                           S_, 200, 1600, cb, 0, br, 1, 0, 0, 0);

        featpart<<<dim3(200, 8), 256>>>(fw, br);
    }

    finalize<<<2, 256>>>(fb, out);
}

// round 9
// speedup vs baseline: 1.4472x; 1.4472x over previous
#include <cuda_runtime.h>
#include <math.h>

#define NB 2049
#define S_ 2048
#define W_ 64
#define D_ 300
#define M_ 100
#define H_ 8
#define D2_ 200
#define V_ 50000
#define RSQ 0.07071067811865475f   // 1/sqrt(200)

#define RPB 28                     // rows per LSTM block
#define RH 14                      // rows per thread-half

// ----------------------------- device scratch ------------------------------
__device__ float g_EW[V_ * 800];          // emb @ [w_ih_f | w_ih_b]^T
__device__ float g_hid[NB * D2_];         // [h_f | h_b]
__device__ float g_hv[D2_];
__device__ float g_logit[S_];
__device__ float g_prob[S_];
__device__ float g_att[S_ * D2_];
__device__ float g_Qa[H_ * S_ * D2_];
__device__ float g_Ka[H_ * S_ * D2_];
__device__ float g_Va[H_ * S_ * D2_];
__device__ float g_Qc[H_ * S_ * D2_];
__device__ float g_Kc[H_ * S_ * D2_];
__device__ float g_Vc[H_ * S_ * D2_];
__device__ float g_SC[33554432];          // 8 * 2048 * 2048 scores -> P in place
__device__ float g_mx[H_ * S_];
__device__ float g_iZ[H_ * S_];
__device__ float g_cat[S_ * H_ * D2_];    // out in cat layout [s][h*200+o]
__device__ float g_mh[S_ * D2_];
__device__ float g_fp[2 * 8 * D2_];
__device__ int   g_idx[2][S_];
__device__ int   g_n[2];

// ------------------------------ generic SGEMM ------------------------------
#define BM 64
#define BN 64
#define BK 16

__global__ void sgemm(const float* __restrict__ A, int lda, long long sA,
                      const float* __restrict__ B, int ldb, long long sB, int transB,
                      float* __restrict__ C, int ldc, long long sC,
                      int M, int N, int K,
                      const float* __restrict__ bias, int sBias,
                      int limBr, int limRows, int limCols, int capK, int epi)
{
    int bz = blockIdx.z;
    int m0 = blockIdx.y * BM;
    int n0 = blockIdx.x * BN;
    if (limBr >= 0) {
        int lim = g_n[limBr];
        if (limRows && m0 >= lim) return;
        if (limCols && n0 >= lim) return;
        if (capK) { int kc = (lim + 15) & ~15; if (kc < K) K = kc; }
    }
    A += (long long)bz * sA;
    B += (long long)bz * sB;
    C += (long long)bz * sC;

    __shared__ __align__(16) float As[BK][BM + 4];
    __shared__ __align__(16) float Bs[BK][BN + 4];
    int tid = threadIdx.x;            // 256 threads
    int tr = tid >> 4, tc = tid & 15;
    float acc[4][4] = {};

    for (int k0 = 0; k0 < K; k0 += BK) {
#pragma unroll
        for (int i = 0; i < 4; i++) {
            int e = tid + i * 256;
            int m = e >> 4, k = e & 15;
            int gm = m0 + m, gk = k0 + k;
            As[k][m] = (gm < M && gk < K) ? A[(long long)gm * lda + gk] : 0.f;
        }
        if (transB) {
#pragma unroll
            for (int i = 0; i < 4; i++) {
                int e = tid + i * 256;
                int nn = e >> 4, k = e & 15;
                int gn = n0 + nn, gk = k0 + k;
                Bs[k][nn] = (gn < N && gk < K) ? B[(long long)gn * ldb + gk] : 0.f;
            }
        } else {
#pragma unroll
            for (int i = 0; i < 4; i++) {
                int e = tid + i * 256;
                int k = e >> 6, nn = e & 63;
                int gk = k0 + k, gn = n0 + nn;
                Bs[k][nn] = (gk < K && gn < N) ? B[(long long)gk * ldb + gn] : 0.f;
            }
        }
        __syncthreads();
#pragma unroll
        for (int k = 0; k < BK; k++) {
            float4 av = *reinterpret_cast<const float4*>(&As[k][tr * 4]);
            float4 bv = *reinterpret_cast<const float4*>(&Bs[k][tc * 4]);
            float a0 = av.x, a1 = av.y, a2 = av.z, a3 = av.w;
            float b0 = bv.x, b1 = bv.y, b2 = bv.z, b3 = bv.w;
            acc[0][0] += a0 * b0; acc[0][1] += a0 * b1; acc[0][2] += a0 * b2; acc[0][3] += a0 * b3;
            acc[1][0] += a1 * b0; acc[1][1] += a1 * b1; acc[1][2] += a1 * b2; acc[1][3] += a1 * b3;
            acc[2][0] += a2 * b0; acc[2][1] += a2 * b1; acc[2][2] += a2 * b2; acc[2][3] += a2 * b3;
            acc[3][0] += a3 * b0; acc[3][1] += a3 * b1; acc[3][2] += a3 * b2; acc[3][3] += a3 * b3;
        }
        __syncthreads();
    }
#pragma unroll
    for (int i = 0; i < 4; i++) {
        int gm = m0 + tr * 4 + i;
        if (gm >= M) continue;
#pragma unroll
        for (int j = 0; j < 4; j++) {
            int gn = n0 + tc * 4 + j;
            if (gn >= N) continue;
            float v = acc[i][j];
            if (bias) v += bias[bz * sBias + gn];
            if (epi == 1) v *= RSQ;
            else if (epi == 2) v = (1.f - v) * RSQ;
            C[(long long)gm * ldc + gn] = v;
        }
    }
}

// ------------------------- fused all-timestep LSTM --------------------------
// grid (74, 2dirs), 256 threads, dyn smem: W^T (100x401) + hT (100x33) + bc + toks.
// Each block owns 28 rows of one direction for ALL 64 timesteps. c in registers.
__global__ void lstm_all(const int* __restrict__ rsent, const int* __restrict__ body,
                         const float* __restrict__ whf, const float* __restrict__ whb,
                         const float* __restrict__ bihf, const float* __restrict__ bhhf,
                         const float* __restrict__ bihb, const float* __restrict__ bhhb)
{
    extern __shared__ float sh[];
    float* Wsh = sh;                    // [100][401]  Wsh[m*401+j] = whh[j][m]
    float* hT  = sh + 40100;            // [100][33]   hT[m*33+r]
    float* bcs = sh + 43400;            // [400]
    int*   toks = (int*)(sh + 43800);   // [28]

    int dir = blockIdx.y;
    int n0 = blockIdx.x * RPB;
    int tid = threadIdx.x;              // 256

    const float* wh = dir ? whb : whf;
    const float* bi = dir ? bihb : bihf;
    const float* bh = dir ? bhhb : bhhf;

    // transpose W into smem (coalesced global reads)
    for (int e = tid; e < 40000; e += 256) {
        int j = e / 100, m = e - j * 100;
        Wsh[m * 401 + j] = wh[e];
    }
    for (int j = tid; j < 400; j += 256) bcs[j] = bi[j] + bh[j];
    for (int e = tid; e < 3300; e += 256) hT[e] = 0.f;
    __syncthreads();

    int m2 = tid & 127;                 // gate index 0..99 (if <100)
    int half = tid >> 7;                // 0 or 1
    int rbase = half * RH;
    bool act = (m2 < 100);

    float c[RH];
#pragma unroll
    for (int r = 0; r < RH; r++) c[r] = 0.f;

    for (int t = 0; t < 64; t++) {
        int w = dir ? (63 - t) : t;
        if (tid < RPB) {
            int n = n0 + tid;
            if (n >= NB) n = NB - 1;
            toks[tid] = (n == 0) ? rsent[w] : body[(n - 1) * W_ + w];
        }
        __syncthreads();

        float acc[4][RH];
        if (act) {
            // init: bias + EW gather
#pragma unroll
            for (int jo = 0; jo < 4; jo++) {
                int j = m2 + jo * 100;
                float bj = bcs[j];
#pragma unroll
                for (int r = 0; r < RH; r++)
                    acc[jo][r] = bj + g_EW[toks[rbase + r] * 800 + dir * 400 + j];
            }
            // h @ Whh^T
            for (int m = 0; m < 100; m++) {
                float w0 = Wsh[m * 401 + m2];
                float w1 = Wsh[m * 401 + m2 + 100];
                float w2 = Wsh[m * 401 + m2 + 200];
                float w3 = Wsh[m * 401 + m2 + 300];
#pragma unroll
                for (int r = 0; r < RH; r++) {
                    float hv = hT[m * 33 + rbase + r];
                    acc[0][r] += w0 * hv;
                    acc[1][r] += w1 * hv;
                    acc[2][r] += w2 * hv;
                    acc[3][r] += w3 * hv;
                }
            }
        }
        __syncthreads();   // all hT reads done before overwrite
        if (act) {
#pragma unroll
            for (int r = 0; r < RH; r++) {
                float fi = 1.f / (1.f + expf(-acc[0][r]));
                float ff = 1.f / (1.f + expf(-acc[1][r]));
                float gg = tanhf(acc[2][r]);
                float fo = 1.f / (1.f + expf(-acc[3][r]));
                c[r] = ff * c[r] + fi * gg;
                hT[m2 * 33 + rbase + r] = fo * tanhf(c[r]);
            }
        }
        __syncthreads();   // new hT visible before next step reads
    }

    // write final h
    if (act) {
#pragma unroll
        for (int r = 0; r < RH; r++) {
            int n = n0 + rbase + r;
            if (n < NB) g_hid[n * D2_ + dir * M_ + m2] = hT[m2 * 33 + rbase + r];
        }
    }
}

// ----------------------------- sim / partition -----------------------------
__global__ void hv_k(const float* __restrict__ simw)
{
    int b = threadIdx.x;
    if (b >= D2_) return;
    float a = 0.f;
    for (int i = 0; i < D2_; i++) a += g_hid[i] * simw[i * D2_ + b];
    g_hv[b] = a;
}

__global__ void logits_k(const float* __restrict__ simb)
{
    __shared__ float hv[D2_];
    int tid = threadIdx.x;
    if (tid < D2_) hv[tid] = g_hv[tid];
    __syncthreads();
    int warp = tid >> 5, lane = tid & 31;
    int s = blockIdx.x * 8 + warp;
    const float* row = g_hid + (long long)(s + 1) * D2_;
    float a = 0.f;
    for (int b = lane; b < D2_; b += 32) a += hv[b] * row[b];
#pragma unroll
    for (int o = 16; o; o >>= 1) a += __shfl_down_sync(0xffffffffu, a, o);
    if (lane == 0) g_logit[s] = a + simb[0];
}

__global__ void softpart()
{
    __shared__ float sg[S_];
    __shared__ float redm[32];
    __shared__ float reds[32];
    __shared__ int cnt[1024];
    int tid = threadIdx.x;           // 1024
    for (int s = tid; s < S_; s += 1024) {
        float l = g_logit[s];
        sg[s] = 1.f / (1.f + expf(-l));
    }
    __syncthreads();
    float m = fmaxf(sg[tid], sg[tid + 1024]);
#pragma unroll
    for (int o = 16; o; o >>= 1) m = fmaxf(m, __shfl_xor_sync(0xffffffffu, m, o));
    if ((tid & 31) == 0) redm[tid >> 5] = m;
    __syncthreads();
    if (tid < 32) {
        float v = redm[tid];
#pragma unroll
        for (int o = 16; o; o >>= 1) v = fmaxf(v, __shfl_xor_sync(0xffffffffu, v, o));
        if (tid == 0) redm[0] = v;
    }
    __syncthreads();
    float mx = redm[0];
    float z = expf(sg[tid] - mx) + expf(sg[tid + 1024] - mx);
#pragma unroll
    for (int o = 16; o; o >>= 1) z += __shfl_xor_sync(0xffffffffu, z, o);
    if ((tid & 31) == 0) reds[tid >> 5] = z;
    __syncthreads();
    if (tid < 32) {
        float v = reds[tid];
#pragma unroll
        for (int o = 16; o; o >>= 1) v += __shfl_xor_sync(0xffffffffu, v, o);
        if (tid == 0) reds[0] = v;
    }
    __syncthreads();
    float invZ = 1.f / reds[0];
    for (int s = tid; s < S_; s += 1024) g_prob[s] = expf(sg[s] - mx) * invZ;

    int a = (sg[2 * tid] >= 0.5f) ? 1 : 0;
    int b = (sg[2 * tid + 1] >= 0.5f) ? 1 : 0;
    cnt[tid] = a + b;
    __syncthreads();
    for (int off = 1; off < 1024; off <<= 1) {
        int v = cnt[tid];
        int u = (tid >= off) ? cnt[tid - off] : 0;
        __syncthreads();
        cnt[tid] = v + u;
        __syncthreads();
    }
    int pre = (tid > 0) ? cnt[tid - 1] : 0;
    int tot = cnt[1023];
    int s0 = 2 * tid, s1 = 2 * tid + 1;
    if (a) g_idx[0][pre] = s0; else g_idx[1][s0 - pre] = s0;
    int pre1 = pre + a;
    if (b) g_idx[0][pre1] = s1; else g_idx[1][s1 - pre1] = s1;
    if (tid == 0) { g_n[0] = tot; g_n[1] = S_ - tot; }
}

__global__ void attend_k()
{
    int s = blockIdx.x;
    float p = g_prob[s];
    for (int o = threadIdx.x; o < D2_; o += 256)
        g_att[s * D2_ + o] = p * g_hid[(s + 1) * D2_ + o];
}

// -------------------------- branch-local kernels ---------------------------
__global__ void compact(int br)
{
    int p = blockIdx.x;
    if (p >= g_n[br]) return;
    int src = g_idx[br][p];
    for (int e = threadIdx.x; e < H_ * D2_; e += 192) {
        int h = e / D2_, o = e - h * D2_;
        long long di = (long long)h * (S_ * D2_) + (long long)p * D2_ + o;
        long long si = (long long)h * (S_ * D2_) + (long long)src * D2_ + o;
        g_Qc[di] = g_Qa[si];
        g_Kc[di] = g_Ka[si];
        g_Vc[di] = g_Va[si];
    }
}

__global__ void colstats(int br)
{
    int n = g_n[br];
    int t = blockIdx.x * 128 + threadIdx.x;
    if (t >= n) return;
    int h = blockIdx.y;
    const float* base = g_SC + (long long)h * S_ * S_ + t;
    float m = -1e30f;
    for (int s = 0; s < n; s++) m = fmaxf(m, base[(long long)s * S_]);
    float z = 0.f;
    for (int s = 0; s < n; s++) z += expf(base[(long long)s * S_] - m);
    g_mx[h * S_ + t] = m;
    g_iZ[h * S_ + t] = 1.f / z;
}

__global__ void pnorm(int br)
{
    int n = g_n[br];
    int s = blockIdx.y;
    if (s >= n) return;
    int capn = (n + 15) & ~15;
    int t = blockIdx.x * 256 + threadIdx.x;
    if (t >= capn) return;
    int h = blockIdx.z;
    long long ix = (long long)h * S_ * S_ + (long long)s * S_ + t;
    float v = 0.f;
    if (t < n) v = expf(g_SC[ix] - g_mx[h * S_ + t]) * g_iZ[h * S_ + t];
    g_SC[ix] = v;
}

__global__ void featpart(const float* __restrict__ fw, int br)
{
    int n = g_n[br];
    int j = blockIdx.x;
    int ch = blockIdx.y;
    int per = (n + 7) / 8;
    int s0 = ch * per;
    int s1 = s0 + per; if (s1 > n) s1 = n;
    if (s0 > n) s0 = n;
    float acc = 0.f;
    const float* base = fw + (long long)j * (S_ * D2_);
    for (long long e = (long long)s0 * D2_ + threadIdx.x; e < (long long)s1 * D2_; e += 256)
        acc += g_mh[e] * base[e];
    __shared__ float red[8];
#pragma unroll
    for (int o = 16; o; o >>= 1) acc += __shfl_xor_sync(0xffffffffu, acc, o);
    if ((threadIdx.x & 31) == 0) red[threadIdx.x >> 5] = acc;
    __syncthreads();
    if (threadIdx.x < 8) {
        float v = red[threadIdx.x];
#pragma unroll
        for (int o = 4; o; o >>= 1) v += __shfl_xor_sync(0x000000ffu, v, o);
        if (threadIdx.x == 0) g_fp[(br * 8 + ch) * D2_ + j] = v;
    }
}

__global__ void finalize(const float* __restrict__ fb, float* __restrict__ out)
{
    int i = blockIdx.x * 256 + threadIdx.x;
    if (i >= 400) return;
    int br = i / 200, j = i - br * 200;
    float a = fb[j];
    for (int c = 0; c < 8; c++) a += g_fp[(br * 8 + c) * D2_ + j];
    out[i] = a;
}

// --------------------------------- launcher --------------------------------
extern "C" void kernel_launch(void* const* d_in, const int* in_sizes, int n_in,
                              void* d_out, int out_size)
{
    const int*   rsent = (const int*)d_in[0];
    const int*   body  = (const int*)d_in[1];
    const float* emb   = (const float*)d_in[2];
    const float* wihf  = (const float*)d_in[3];
    const float* whhf  = (const float*)d_in[4];
    const float* bihf  = (const float*)d_in[5];
    const float* bhhf  = (const float*)d_in[6];
    const float* wihb  = (const float*)d_in[7];
    const float* whhb  = (const float*)d_in[8];
    const float* bihb  = (const float*)d_in[9];
    const float* bhhb  = (const float*)d_in[10];
    const float* simw  = (const float*)d_in[11];
    const float* simb  = (const float*)d_in[12];
    const float* qw    = (const float*)d_in[13];
    const float* qb    = (const float*)d_in[14];
    const float* kw    = (const float*)d_in[15];
    const float* kb    = (const float*)d_in[16];
    const float* vw    = (const float*)d_in[17];
    const float* vb    = (const float*)d_in[18];
    const float* cw    = (const float*)d_in[19];
    const float* cb    = (const float*)d_in[20];
    const float* fw    = (const float*)d_in[21];
    const float* fb    = (const float*)d_in[22];
    float* out = (float*)d_out;

    float *pEW, *pAtt, *pQa, *pKa, *pVa, *pQc, *pKc, *pVc, *pSC, *pCat, *pMh;
    cudaGetSymbolAddress((void**)&pEW, g_EW);
    cudaGetSymbolAddress((void**)&pAtt, g_att);
    cudaGetSymbolAddress((void**)&pQa, g_Qa);
    cudaGetSymbolAddress((void**)&pKa, g_Ka);
    cudaGetSymbolAddress((void**)&pVa, g_Va);
    cudaGetSymbolAddress((void**)&pQc, g_Qc);
    cudaGetSymbolAddress((void**)&pKc, g_Kc);
    cudaGetSymbolAddress((void**)&pVc, g_Vc);
    cudaGetSymbolAddress((void**)&pSC, g_SC);
    cudaGetSymbolAddress((void**)&pCat, g_cat);
    cudaGetSymbolAddress((void**)&pMh, g_mh);

    // EW = emb @ w_ih^T  (per direction)
    dim3 ge(7, 782, 1);
    sgemm<<<ge, 256>>>(emb, 300, 0, wihf, 300, 0, 1, pEW,       800, 0,
                       V_, 400, 300, nullptr, 0, -1, 0, 0, 0, 0);
    sgemm<<<ge, 256>>>(emb, 300, 0, wihb, 300, 0, 1, pEW + 400, 800, 0,
                       V_, 400, 300, nullptr, 0, -1, 0, 0, 0, 0);

    // fused all-timestep LSTM: one block per SM
    const int SMEM_LSTM = (40100 + 3300 + 400) * 4 + RPB * 4;
    cudaFuncSetAttribute(lstm_all, cudaFuncAttributeMaxDynamicSharedMemorySize, SMEM_LSTM);
    lstm_all<<<dim3(74, 2), 256, SMEM_LSTM>>>(rsent, body, whhf, whhb,
                                              bihf, bhhf, bihb, bhhb);

    hv_k<<<1, 256>>>(simw);
    logits_k<<<256, 256>>>(simb);
    softpart<<<1, 1024>>>();
    attend_k<<<2048, 256>>>();

    // Q/K/V on full attend, h-batched (z=8)
    dim3 gq(4, 32, 8);
    sgemm<<<gq, 256>>>(pAtt, 200, 0, qw, 200, 40000LL, 1, pQa, 200, 409600LL,
                       S_, 200, 200, qb, 200, -1, 0, 0, 0, 0);
    sgemm<<<gq, 256>>>(pAtt, 200, 0, kw, 200, 40000LL, 1, pKa, 200, 409600LL,
                       S_, 200, 200, kb, 200, -1, 0, 0, 0, 0);
    sgemm<<<gq, 256>>>(pAtt, 200, 0, vw, 200, 40000LL, 1, pVa, 200, 409600LL,
                       S_, 200, 200, vb, 200, -1, 0, 0, 0, 0);

    for (int br = 0; br < 2; br++) {
        compact<<<2048, 192>>>(br);

        dim3 gs(32, 32, 8);
        sgemm<<<gs, 256>>>(pQc, 200, 409600LL, pKc, 200, 409600LL, 1,
                           pSC, 2048, 4194304LL, S_, S_, 200,
                           nullptr, 0, br, 1, 1, 0, (br == 0) ? 1 : 2);

        colstats<<<dim3(16, 8), 128>>>(br);
        pnorm<<<dim3(8, 2048, 8), 256>>>(br);

        dim3 go(4, 32, 8);
        sgemm<<<go, 256>>>(pSC, 2048, 4194304LL, pVc, 200, 409600LL, 0,
                           pCat, 1600, 200LL, S_, 200, S_,
                           nullptr, 0, br, 1, 0, 1, 0);

        dim3 gm(4, 32, 1);
        sgemm<<<gm, 256>>>(pCat, 1600, 0, cw, 1600, 0, 1, pMh, 200, 0,
                           S_, 200, 1600, cb, 0, br, 1, 0, 0, 0);

        featpart<<<dim3(200, 8), 256>>>(fw, br);
    }

    finalize<<<2, 256>>>(fb, out);
}